// round 12
// baseline (speedup 1.0000x reference)
#include <cuda_runtime.h>

#define NH 128
#define NI 64
#define NO 10
#define NB 128

// ---- packed f32x2 helpers (sm_100+ PTX) ----
__device__ __forceinline__ unsigned long long ffma2(unsigned long long a,
                                                    unsigned long long b,
                                                    unsigned long long c) {
    unsigned long long d;
    asm("fma.rn.f32x2 %0, %1, %2, %3;" : "=l"(d) : "l"(a), "l"(b), "l"(c));
    return d;
}
__device__ __forceinline__ unsigned long long packf2(float lo, float hi) {
    unsigned long long r;
    asm("mov.b64 %0, {%1, %2};" : "=l"(r) : "f"(lo), "f"(hi));
    return r;
}
__device__ __forceinline__ float2 unpackf2(unsigned long long v) {
    float2 f;
    asm("mov.b64 {%0, %1}, %2;" : "=f"(f.x), "=f"(f.y) : "l"(v));
    return f;
}

// ============================================================
// Fully fused RNN scan: grid = NB (1 chain/SM), block = 256 (8 warps).
// The 192-term dot (h[128] @ Whh + x[64] @ Wxh) is K-split 8 ways:
//   warp w: h-slice [hs, hs+16) with hs = 32*(w&3) + 16*(w>>2),
//           x-slice [8w, 8w+8).
// Lane l computes partials for columns 4l..4l+3 (12 FFMA2 each).
// hs is chosen so each warp's phase-A h read slice is inside its own
// phase-B write range [32*(w&3), +32) -> h handoff needs no second
// barrier (duplicate same-value writes from tid and tid+128 halves
// are bitwise identical; own-warp ordering via __syncwarp).
// x[t] comes from an 8-deep shared ring; warps 0-1 feed it with a
// 2-step LDG->STS distance (~1150 cyc, covers DRAM latency).
// One __syncthreads per step. No K1, no g_xw round-trip.
// ============================================================
__global__ void __launch_bounds__(256, 1) rnn_fused_kernel(
    const float* __restrict__ x,    // [S, B, NI]
    const float* __restrict__ Wxh,  // [NI, NH]
    const float* __restrict__ Whh,  // [NH, NH]
    const float* __restrict__ Why,  // [NH, NO]
    const float* __restrict__ bh,   // [NH]
    const float* __restrict__ by,   // [NO]
    float* __restrict__ out,        // logits [B,NO] then h [S,B,NH]
    int seq)
{
    const int b   = blockIdx.x;
    const int tid = threadIdx.x;
    const int w   = tid >> 5;
    const int l   = tid & 31;
    const int hs  = 32 * (w & 3) + 16 * (w >> 2);  // h-slice start
    const int xs  = 8 * w;                          // x-slice start
    const int cr  = tid & 127;                      // reduce column

    // ---- weights: 8 h-pairs + 4 x-pairs per column, 4 columns ----
    unsigned long long wph[4][8], wpx[4][4];
#pragma unroll
    for (int c = 0; c < 4; c++) {
        const int col = 4 * l + c;
#pragma unroll
        for (int kk = 0; kk < 8; kk++) {
            const int k = hs + 2 * kk;
            wph[c][kk] = packf2(Whh[k * NH + col], Whh[(k + 1) * NH + col]);
        }
#pragma unroll
        for (int ii = 0; ii < 4; ii++) {
            const int i = xs + 2 * ii;
            wpx[c][ii] = packf2(Wxh[i * NH + col], Wxh[(i + 1) * NH + col]);
        }
    }
    const float bias = bh[cr];

    __shared__ __align__(16) float hbuf[2][NH];      // parity-swapped h
    __shared__ __align__(16) float part[2][8][NH];   // double-buffered partials
    __shared__ __align__(16) float xring[8][NI];     // x ring, slot t&7

    if (tid < NH) hbuf[0][tid] = 0.0f;

    // ---- prime x ring: slots 0..3 = x[0..3]; xq2 = {x[4], x[5]} ----
    const float* xb = x + (long long)b * NI;
    float xq2[2] = {0.f, 0.f};
    if (tid < NI) {
#pragma unroll
        for (int q = 0; q < 4; q++) {
            int tq = (q < seq) ? q : (seq - 1);
            xring[q][tid] = xb[(long long)tq * NB * NI + tid];
        }
        int t4 = (4 < seq) ? 4 : (seq - 1);
        int t5 = (5 < seq) ? 5 : (seq - 1);
        xq2[0] = xb[(long long)t4 * NB * NI + tid];
        xq2[1] = xb[(long long)t5 * NB * NI + tid];
    }

    float* h_out = out + NB * NO;
    __syncthreads();

#pragma unroll 4
    for (int t = 0; t < seq; t++) {
        const int pb = t & 1;

        // ---- phase A: own h slice (4 LDS.128) + own x slice (2 LDS.128) ----
        ulonglong2 hv[4], xv[2];
        const ulonglong2* h2 =
            reinterpret_cast<const ulonglong2*>(&hbuf[pb][hs]);
#pragma unroll
        for (int m = 0; m < 4; m++) hv[m] = h2[m];
        const ulonglong2* x2 =
            reinterpret_cast<const ulonglong2*>(&xring[t & 7][xs]);
#pragma unroll
        for (int m = 0; m < 2; m++) xv[m] = x2[m];

        // ---- 24-term partials for 4 columns (48 FFMA2, depth 12) ----
        unsigned long long a0 = 0ull, a1 = 0ull, a2 = 0ull, a3 = 0ull;
#pragma unroll
        for (int m = 0; m < 4; m++) {
            a0 = ffma2(hv[m].x, wph[0][2 * m], a0);
            a0 = ffma2(hv[m].y, wph[0][2 * m + 1], a0);
            a1 = ffma2(hv[m].x, wph[1][2 * m], a1);
            a1 = ffma2(hv[m].y, wph[1][2 * m + 1], a1);
            a2 = ffma2(hv[m].x, wph[2][2 * m], a2);
            a2 = ffma2(hv[m].y, wph[2][2 * m + 1], a2);
            a3 = ffma2(hv[m].x, wph[3][2 * m], a3);
            a3 = ffma2(hv[m].y, wph[3][2 * m + 1], a3);
        }
#pragma unroll
        for (int m = 0; m < 2; m++) {
            a0 = ffma2(xv[m].x, wpx[0][2 * m], a0);
            a0 = ffma2(xv[m].y, wpx[0][2 * m + 1], a0);
            a1 = ffma2(xv[m].x, wpx[1][2 * m], a1);
            a1 = ffma2(xv[m].y, wpx[1][2 * m + 1], a1);
            a2 = ffma2(xv[m].x, wpx[2][2 * m], a2);
            a2 = ffma2(xv[m].y, wpx[2][2 * m + 1], a2);
            a3 = ffma2(xv[m].x, wpx[3][2 * m], a3);
            a3 = ffma2(xv[m].y, wpx[3][2 * m + 1], a3);
        }
        float2 f0 = unpackf2(a0), f1 = unpackf2(a1),
               f2 = unpackf2(a2), f3 = unpackf2(a3);
        float4 pr = make_float4(f0.x + f0.y, f1.x + f1.y,
                                f2.x + f2.y, f3.x + f3.y);
        *reinterpret_cast<float4*>(&part[pb][w][4 * l]) = pr;  // conflict-free

        // ---- x ring feed (warps 0-1, uniform per warp) ----
        if (tid < NI) {
            xring[(t + 4) & 7][tid] = xq2[t & 1];   // x[t+4], loaded 2 steps ago
            int tf = t + 6;
            if (tf >= seq) tf = seq - 1;
            xq2[t & 1] = xb[(long long)tf * NB * NI + tid];
        }

        __syncthreads();   // the only block barrier per step

        // ---- phase B: reduce 8 partials for column cr (both halves) ----
        float v = (((part[pb][0][cr] + part[pb][1][cr]) +
                    (part[pb][2][cr] + part[pb][3][cr])) +
                   ((part[pb][4][cr] + part[pb][5][cr]) +
                    (part[pb][6][cr] + part[pb][7][cr]))) + bias;

        // R10 tanh: exp + fast reciprocal (proven fastest form)
        float a = fabsf(v);
        float e = __expf(-2.0f * a);
        float r = __fdividef(1.0f - e, 1.0f + e);
        float h = copysignf(r, v);

        hbuf[pb ^ 1][cr] = h;   // dup same-value write by tid & tid+128: benign
        if (tid < NH)
            h_out[((long long)t * NB + b) * NH + cr] = h;  // coalesced 512 B
        __syncwarp();
    }

    __syncthreads();
    // ---- logits = h_last @ Why + by ----
    if (tid < NO) {
        float acc = by[tid];
#pragma unroll 8
        for (int k = 0; k < NH; k++)
            acc = fmaf(hbuf[seq & 1][k], Why[k * NO + tid], acc);
        out[b * NO + tid] = acc;
    }
}

extern "C" void kernel_launch(void* const* d_in, const int* in_sizes, int n_in,
                              void* d_out, int out_size) {
    const float* x   = (const float*)d_in[0];
    const float* Wxh = (const float*)d_in[1];
    const float* Whh = (const float*)d_in[2];
    const float* Why = (const float*)d_in[3];
    const float* bh  = (const float*)d_in[4];
    const float* by  = (const float*)d_in[5];
    float* out = (float*)d_out;

    int seq = in_sizes[0] / (NB * NI);  // 2048

    rnn_fused_kernel<<<NB, 256>>>(x, Wxh, Whh, Why, bh, by, out, seq);
}

// round 14
// speedup vs baseline: 1.0805x; 1.0805x over previous
#include <cuda_runtime.h>

#define NH 128
#define NI 64
#define NO 10
#define NB 128
#define S_MAX 2048

// 128 MiB scratch for the precomputed input projection xW[S,B,H].
__device__ __align__(16) float g_xw[(size_t)S_MAX * NB * NH];

// ---- packed f32x2 helpers (sm_100+ PTX) ----
__device__ __forceinline__ unsigned long long ffma2(unsigned long long a,
                                                    unsigned long long b,
                                                    unsigned long long c) {
    unsigned long long d;
    asm("fma.rn.f32x2 %0, %1, %2, %3;" : "=l"(d) : "l"(a), "l"(b), "l"(c));
    return d;
}
__device__ __forceinline__ unsigned long long packf2(float lo, float hi) {
    unsigned long long r;
    asm("mov.b64 %0, {%1, %2};" : "=l"(r) : "f"(lo), "f"(hi));
    return r;
}
__device__ __forceinline__ float2 unpackf2(unsigned long long v) {
    float2 f;
    asm("mov.b64 {%0, %1}, %2;" : "=f"(f.x), "=f"(f.y) : "l"(v));
    return f;
}

// ============================================================
// K1 (persistent): xW[s,b,j] = x[s,b,:] @ Wxh[:,j] + bh[j]
// grid = 444 persistent CTAs (3/SM), block = 256 (6 warps/SMSP).
// Thread: column pair (2jj, 2jj+1), jj = tid&63; row group p = tid>>6.
// Weights (64 packed regs) loaded ONCE per CTA, amortized over ~9
// tiles. Tile = (s, 64 batch rows): x staged in 16 KB shared; per row
// 16 broadcast LDS.128 -> 64 FFMA2 -> 1 coalesced STG.64.
// ============================================================
__global__ void __launch_bounds__(256, 1) xw_gemm_kernel(
    const float* __restrict__ x, const float* __restrict__ Wxh,
    const float* __restrict__ bh, int seq)
{
    const int tid = threadIdx.x;
    const int jj  = tid & 63;   // column pair index
    const int p   = tid >> 6;   // row group 0..3
    const int c0  = 2 * jj;

    // weights for 2 columns, packed by k-pairs
    unsigned long long w2[2][NI / 2];
#pragma unroll
    for (int ci = 0; ci < 2; ci++) {
        const int col = c0 + ci;
#pragma unroll
        for (int m = 0; m < NI / 2; m++)
            w2[ci][m] = packf2(Wxh[(2 * m) * NH + col],
                               Wxh[(2 * m + 1) * NH + col]);
    }
    const float2 bias2 = make_float2(bh[c0], bh[c0 + 1]);

    __shared__ __align__(16) float xs[64 * NI];  // 16 KB

    const int ntiles = 2 * seq;  // (s, half) tiles of 64 batch rows
    for (int tile = blockIdx.x; tile < ntiles; tile += gridDim.x) {
        const int s  = tile >> 1;
        const int bb = (tile & 1) * 64;

        __syncthreads();  // previous tile's reads done before overwrite
        const float4* xin = reinterpret_cast<const float4*>(
            x + ((long long)s * NB + bb) * NI);
        float4* xs4 = reinterpret_cast<float4*>(xs);
#pragma unroll
        for (int i = tid; i < 64 * NI / 4; i += 256) xs4[i] = xin[i];
        __syncthreads();

        float* orow = g_xw + ((long long)s * NB + bb) * NH;
#pragma unroll
        for (int r = p; r < 64; r += 4) {
            const ulonglong2* xr =
                reinterpret_cast<const ulonglong2*>(xs + r * NI);
            unsigned long long a00 = 0ull, a01 = 0ull;  // col c0
            unsigned long long a10 = 0ull, a11 = 0ull;  // col c0+1
#pragma unroll
            for (int m = 0; m < NI / 4; m++) {
                ulonglong2 xv = xr[m];  // broadcast LDS.128 (same row per warp)
                a00 = ffma2(xv.x, w2[0][2 * m], a00);
                a01 = ffma2(xv.y, w2[0][2 * m + 1], a01);
                a10 = ffma2(xv.x, w2[1][2 * m], a10);
                a11 = ffma2(xv.y, w2[1][2 * m + 1], a11);
            }
            float2 f00 = unpackf2(a00), f01 = unpackf2(a01);
            float2 f10 = unpackf2(a10), f11 = unpackf2(a11);
            float2 o = make_float2((f00.x + f00.y) + (f01.x + f01.y) + bias2.x,
                                   (f10.x + f10.y) + (f11.x + f11.y) + bias2.y);
            *reinterpret_cast<float2*>(&orow[r * NH + c0]) = o;  // STG.64
        }
    }
}

// ============================================================
// K2 (R10 verbatim): sequential scan with K-split partial exchange.
// grid = NB (1 chain per CTA/SM), block = 128.
// Warp w owns columns [32w,32w+32) AND K-slice [32w,32w+32).
// tanh via exp + __fdividef (MUFU.RCP; denominator in [1,2] -> ~2 ulp).
// ============================================================
__global__ void __launch_bounds__(NH, 1) rnn_scan_kernel(
    const float* __restrict__ Whh, const float* __restrict__ Why,
    const float* __restrict__ bh, const float* __restrict__ by,
    float* __restrict__ out, int seq)
{
    const int b   = blockIdx.x;
    const int tid = threadIdx.x;
    const int w   = tid >> 5;   // warp = K-slice index
    const int l   = tid & 31;

    // Weights: wp[c][kk] packs Whh[k][4l+c] for k-pair (32w+2kk, 32w+2kk+1).
    unsigned long long wp[4][16];
#pragma unroll
    for (int c = 0; c < 4; c++) {
        const int col = 4 * l + c;
#pragma unroll
        for (int kk = 0; kk < 16; kk++) {
            const int k = 32 * w + 2 * kk;
            wp[c][kk] = packf2(Whh[k * NH + col], Whh[(k + 1) * NH + col]);
        }
    }
    const float bias = bh[tid];

    __shared__ __align__(16) float hbuf[2][NH];        // parity-swapped h
    __shared__ __align__(16) float part[2][4][NH];     // double-buffered partials
    hbuf[0][tid] = 0.0f;

    // xw prefetch ring (depth 4) for OWN column tid
    const float* xwb = g_xw + (long long)b * NH + tid;
    float xq[4];
#pragma unroll
    for (int q = 0; q < 4; q++)
        xq[q] = (q < seq) ? xwb[(long long)q * NB * NH] : 0.0f;

    float* h_out = out + NB * NO;
    __syncthreads();

#pragma unroll 4
    for (int t = 0; t < seq; t++) {
        const int pb = t & 1;

        // ---- batched load of OWN warp's h slice (8 broadcast LDS.128) ----
        ulonglong2 hv[8];
        const ulonglong2* h2 =
            reinterpret_cast<const ulonglong2*>(&hbuf[pb][32 * w]);
#pragma unroll
        for (int m = 0; m < 8; m++) hv[m] = h2[m];

        // ---- 32-term partials for columns 4l..4l+3 (64 FFMA2) ----
        unsigned long long a0 = 0ull, a1 = 0ull, a2 = 0ull, a3 = 0ull;
#pragma unroll
        for (int m = 0; m < 8; m++) {
            a0 = ffma2(hv[m].x, wp[0][2 * m], a0);
            a0 = ffma2(hv[m].y, wp[0][2 * m + 1], a0);
            a1 = ffma2(hv[m].x, wp[1][2 * m], a1);
            a1 = ffma2(hv[m].y, wp[1][2 * m + 1], a1);
            a2 = ffma2(hv[m].x, wp[2][2 * m], a2);
            a2 = ffma2(hv[m].y, wp[2][2 * m + 1], a2);
            a3 = ffma2(hv[m].x, wp[3][2 * m], a3);
            a3 = ffma2(hv[m].y, wp[3][2 * m + 1], a3);
        }
        float2 f0 = unpackf2(a0), f1 = unpackf2(a1),
               f2 = unpackf2(a2), f3 = unpackf2(a3);
        float4 pr = make_float4(f0.x + f0.y, f1.x + f1.y,
                                f2.x + f2.y, f3.x + f3.y);
        *reinterpret_cast<float4*>(&part[pb][w][4 * l]) = pr;  // conflict-free

        // xw consume + refill (covers DRAM latency across 4 steps)
        const float xwv = xq[t & 3];
        if (t + 4 < seq) xq[t & 3] = xwb[(long long)(t + 4) * NB * NH];

        __syncthreads();

        // ---- reduce 4 partials for OWN column tid ----
        float v = ((part[pb][0][tid] + part[pb][1][tid]) +
                   (part[pb][2][tid] + part[pb][3][tid])) + xwv + bias;

        // tanh: exp2 + fast reciprocal (denominator in [1,2] -> ~2 ulp).
        float a = fabsf(v);
        float e = __expf(-2.0f * a);
        float r = __fdividef(1.0f - e, 1.0f + e);
        float h = copysignf(r, v);

        h_out[((long long)t * NB + b) * NH + tid] = h;  // coalesced 512 B
        hbuf[pb ^ 1][tid] = h;   // own-warp slice; next step reads own slice only
        __syncwarp();
    }

    __syncthreads();
    // ---- logits = h_last @ Why + by ----
    if (tid < NO) {
        float acc = by[tid];
#pragma unroll 8
        for (int k = 0; k < NH; k++)
            acc = fmaf(hbuf[seq & 1][k], Why[k * NO + tid], acc);
        out[b * NO + tid] = acc;
    }
}

extern "C" void kernel_launch(void* const* d_in, const int* in_sizes, int n_in,
                              void* d_out, int out_size) {
    const float* x   = (const float*)d_in[0];
    const float* Wxh = (const float*)d_in[1];
    const float* Whh = (const float*)d_in[2];
    const float* Why = (const float*)d_in[3];
    const float* bh  = (const float*)d_in[4];
    const float* by  = (const float*)d_in[5];
    float* out = (float*)d_out;

    int seq = in_sizes[0] / (NB * NI);  // 2048
    if (seq > S_MAX) seq = S_MAX;

    int ntiles = 2 * seq;
    int grid1 = ntiles < 444 ? ntiles : 444;
    xw_gemm_kernel<<<grid1, 256>>>(x, Wxh, bh, seq);
    rnn_scan_kernel<<<NB, NH>>>(Whh, Why, bh, by, out, seq);
}